// round 5
// baseline (speedup 1.0000x reference)
#include <cuda_runtime.h>
#include <cstdint>

// Depth-to-space r=4, x-major channel ordering:
//   out[b, c, y, x] = in[b, c*16 + 4*(x%4) + (y%4), y/4, x/4]
// in : (16, 4096, 32, 32) fp32, out: (16, 256, 128, 128) fp32.
//
// Each (b,c) pair is a contiguous 64KB in-block -> contiguous 64KB out-block.
// Pipeline per CTA (512 threads, 8 blocks each, double-buffered smem):
//   TMA 1D bulk load 64KB (perfectly linear HBM reads, zero thread LDGs)
//   -> smem permute (conflict-controlled LDS.128 + register transpose)
//   -> dense v8.f32 stores (warp writes 4KB contiguous, full sectors).

#define BLOCK_BYTES 65536
#define SMEM_TOTAL  (2 * BLOCK_BYTES + 16)

__global__ void __launch_bounds__(512, 1) scale_transfer_tma_kernel(
    const float* __restrict__ in, float* __restrict__ out)
{
    extern __shared__ __align__(128) char smem[];
    uint32_t sbase;
    asm("{ .reg .u64 t; cvta.to.shared.u64 t, %1; cvt.u32.u64 %0, t; }"
        : "=r"(sbase) : "l"(smem));
    const uint32_t mbar0 = sbase + 2 * BLOCK_BYTES;
    const uint32_t mbar1 = mbar0 + 8;

    const int tid = threadIdx.x;
    if (tid == 0) {
        asm volatile("mbarrier.init.shared.b64 [%0], 1;" :: "r"(mbar0) : "memory");
        asm volatile("mbarrier.init.shared.b64 [%0], 1;" :: "r"(mbar1) : "memory");
    }
    __syncthreads();

    const long base_blk = (long)blockIdx.x * 8;

    // Prologue: prefetch blocks k=0 (buf0) and k=1 (buf1)
    if (tid == 0) {
#pragma unroll
        for (int k = 0; k < 2; k++) {
            uint32_t mb  = k ? mbar1 : mbar0;
            uint32_t dst = sbase + k * BLOCK_BYTES;
            const float* src = in + (base_blk + k) * 16384;
            asm volatile("mbarrier.arrive.expect_tx.shared.b64 _, [%0], %1;"
                         :: "r"(mb), "r"(BLOCK_BYTES) : "memory");
            asm volatile(
                "cp.async.bulk.shared::cluster.global.mbarrier::complete_tx::bytes "
                "[%0], [%1], %2, [%3];"
                :: "r"(dst), "l"(src), "r"(BLOCK_BYTES), "r"(mb) : "memory");
        }
    }

    const unsigned xq = tid & 3;
    const unsigned y  = tid >> 2;         // 0..127
    const unsigned yr = y & 3;
    const unsigned yb = y >> 2;
    // smem read base (float4 units): channel (4*xr+yr), row yb, cols xq*8..
    const unsigned rq = (yr * 1024u + yb * 32u + xq * 8u) >> 2;
    // out offset within block (floats)
    const unsigned ooff = y * 128u + xq * 32u;

#pragma unroll 1
    for (int k = 0; k < 8; k++) {
        const uint32_t mb  = (k & 1) ? mbar1 : mbar0;
        const unsigned phase = (k >> 1) & 1;

        // wait for buffer full (acquire)
        asm volatile(
            "{\n\t.reg .pred p;\n\t"
            "WL_%=:\n\t"
            "mbarrier.try_wait.parity.acquire.cta.shared::cta.b64 p, [%0], %1, 0x989680;\n\t"
            "@!p bra WL_%=;\n\t}"
            :: "r"(mb), "r"(phase) : "memory");

        const float4* sb = (const float4*)(smem + (k & 1) * BLOCK_BYTES);

        float r[4][8];
#pragma unroll
        for (int xr = 0; xr < 4; xr++) {
            float4 a = sb[rq + xr * 1024u];
            float4 c = sb[rq + xr * 1024u + 1];
            r[xr][0] = a.x; r[xr][1] = a.y; r[xr][2] = a.z; r[xr][3] = a.w;
            r[xr][4] = c.x; r[xr][5] = c.y; r[xr][6] = c.z; r[xr][7] = c.w;
        }

        float* o = out + (base_blk + k) * 16384 + ooff;
#pragma unroll
        for (int j = 0; j < 4; j++) {
            int i0 = 2 * j, i1 = 2 * j + 1;
            asm volatile(
                "st.global.v8.f32 [%0], {%1,%2,%3,%4,%5,%6,%7,%8};"
                :
                : "l"(o + j * 8),
                  "f"(r[0][i0]), "f"(r[1][i0]), "f"(r[2][i0]), "f"(r[3][i0]),
                  "f"(r[0][i1]), "f"(r[1][i1]), "f"(r[2][i1]), "f"(r[3][i1])
                : "memory");
        }

        // all threads done reading this buffer before TMA refills it
        __syncthreads();

        if (tid == 0 && k + 2 < 8) {
            uint32_t dst = sbase + (k & 1) * BLOCK_BYTES;
            const float* src = in + (base_blk + k + 2) * 16384;
            asm volatile("mbarrier.arrive.expect_tx.shared.b64 _, [%0], %1;"
                         :: "r"(mb), "r"(BLOCK_BYTES) : "memory");
            asm volatile(
                "cp.async.bulk.shared::cluster.global.mbarrier::complete_tx::bytes "
                "[%0], [%1], %2, [%3];"
                :: "r"(dst), "l"(src), "r"(BLOCK_BYTES), "r"(mb) : "memory");
        }
    }
}

extern "C" void kernel_launch(void* const* d_in, const int* in_sizes, int n_in,
                              void* d_out, int out_size)
{
    const float* in = (const float*)d_in[0];
    float* out = (float*)d_out;

    cudaFuncSetAttribute(scale_transfer_tma_kernel,
                         cudaFuncAttributeMaxDynamicSharedMemorySize, SMEM_TOTAL);

    // 4096 (b,c) blocks total, 8 per CTA
    scale_transfer_tma_kernel<<<512, 512, SMEM_TOTAL>>>(in, out);
}

// round 6
// speedup vs baseline: 1.0656x; 1.0656x over previous
#include <cuda_runtime.h>
#include <cstdint>

// Depth-to-space r=4, x-major channel ordering:
//   out[b, c, y, x] = in[b, c*16 + 4*(x%4) + (y%4), y/4, x/4]
// in : (16, 4096, 32, 32) fp32  -> 256 MB
// out: (16, 256, 128, 128) fp32 -> 256 MB
//
// Round-2 mapping (best so far: warp covers 8 consecutive output rows dense,
// all accesses full 32B sectors) + isolated refinements:
//   - L2::evict_first on both streams (zero reuse, keep L2 clean)
//   - __launch_bounds__(256,5) to cap regs ~48 and lift occupancy to ~50%

__global__ void __launch_bounds__(256, 5) scale_transfer_v8e_kernel(
    const float* __restrict__ in, float* __restrict__ out)
{
    unsigned tid = blockIdx.x * blockDim.x + threadIdx.x;
    // tid layout: b[4] c[8] y[7] xq[2]  -> 16*256*128*4 = 2,097,152 threads
    unsigned xq = tid & 3;            // 8-float group within 32-float input row
    unsigned y  = (tid >> 2) & 127;
    unsigned c  = (tid >> 9) & 255;
    unsigned b  = tid >> 16;          // note: bits [16..19]

    // fix bit layout: y occupies bits [2..8], c bits [9..16], b bits [17..20]
    c = (tid >> 9) & 255;
    b = tid >> 17;

    unsigned yr = y & 3;
    unsigned yb = y >> 2;

    // input float index; xr channel stride = 4 channels = 4096 floats
    const float* p =
        in + (((b * 4096u + c * 16u + yr) * 32u + yb) * 32u + xq * 8u);

    float r[4][8];
#pragma unroll
    for (int xr = 0; xr < 4; xr++) {
        const float* q = p + xr * 4096;
        asm volatile(
            "ld.global.nc.L2::evict_first.v8.f32 "
            "{%0,%1,%2,%3,%4,%5,%6,%7}, [%8];"
            : "=f"(r[xr][0]), "=f"(r[xr][1]), "=f"(r[xr][2]), "=f"(r[xr][3]),
              "=f"(r[xr][4]), "=f"(r[xr][5]), "=f"(r[xr][6]), "=f"(r[xr][7])
            : "l"(q));
    }

    // output: 32 consecutive floats (x = xq*32 .. xq*32+31) of row (b,c,y)
    float* o = out + (((b * 256u + c) * 128u + y) * 128u + xq * 32u);

#pragma unroll
    for (int j = 0; j < 4; j++) {
        int i0 = 2 * j, i1 = 2 * j + 1;
        asm volatile(
            "st.global.L2::evict_first.v8.f32 "
            "[%0], {%1,%2,%3,%4,%5,%6,%7,%8};"
            :
            : "l"(o + j * 8),
              "f"(r[0][i0]), "f"(r[1][i0]), "f"(r[2][i0]), "f"(r[3][i0]),
              "f"(r[0][i1]), "f"(r[1][i1]), "f"(r[2][i1]), "f"(r[3][i1])
            : "memory");
    }
}

extern "C" void kernel_launch(void* const* d_in, const int* in_sizes, int n_in,
                              void* d_out, int out_size)
{
    const float* in = (const float*)d_in[0];
    float* out = (float*)d_out;

    const int total_threads = 16 * 256 * 128 * 4;  // 2,097,152
    const int block = 256;
    const int grid = total_threads / block;        // 8192

    scale_transfer_v8e_kernel<<<grid, block>>>(in, out);
}